// round 1
// baseline (speedup 1.0000x reference)
#include <cuda_runtime.h>
#include <math.h>

#define N_NODES 50000
#define N_EDGES 400000
#define FD      128
#define FD3     384
#define N_TYPES 100
#define NRBF    20
#define CUTOFF  5.0f
#define PI_F    3.14159265358979323846f
#define BE      64   // edges staged per block-batch

// phi_table[type][3*FD]: silu(emb_table @ w_phi1 + b1) @ w_phi2 + b2
__device__ float g_phi_table[N_TYPES * FD3];

// ---------------------------------------------------------------------------
// Kernel 1: phi table (tiny, 100 blocks)
// ---------------------------------------------------------------------------
__global__ void phi_table_kernel(const float* __restrict__ emb_table,
                                 const float* __restrict__ w_phi1,
                                 const float* __restrict__ b_phi1,
                                 const float* __restrict__ w_phi2,
                                 const float* __restrict__ b_phi2) {
    __shared__ float s_emb[FD];
    __shared__ float s_h[FD];
    int t = blockIdx.x;      // atom type
    int j = threadIdx.x;     // 0..127
    s_emb[j] = emb_table[t * FD + j];
    __syncthreads();
    float acc = b_phi1[j];
#pragma unroll 8
    for (int k = 0; k < FD; k++) acc += s_emb[k] * w_phi1[k * FD + j];
    // silu
    s_h[j] = acc / (1.0f + expf(-acc));
    __syncthreads();
#pragma unroll
    for (int seg = 0; seg < 3; seg++) {
        int c = seg * FD + j;
        float a2 = b_phi2[c];
#pragma unroll 8
        for (int k = 0; k < FD; k++) a2 += s_h[k] * w_phi2[k * FD3 + c];
        g_phi_table[t * FD3 + c] = a2;
    }
}

// ---------------------------------------------------------------------------
// Kernel 2: initialize d_out = [ emb_table[z] (N,128) | eq (N,128,3) ]
// ---------------------------------------------------------------------------
__global__ void init_out_kernel(float* __restrict__ out,
                                const float* __restrict__ emb_table,
                                const float* __restrict__ eq,
                                const int* __restrict__ z) {
    int stride = gridDim.x * blockDim.x;
    int i0 = blockIdx.x * blockDim.x + threadIdx.x;
    const int total1 = N_NODES * FD;
    for (int idx = i0; idx < total1; idx += stride) {
        int node = idx >> 7;
        int f = idx & (FD - 1);
        out[idx] = emb_table[z[node] * FD + f];
    }
    const float4* eq4 = (const float4*)eq;
    float4* out4 = (float4*)(out + total1);
    const int total2 = N_NODES * FD * 3 / 4;
    for (int idx = i0; idx < total2; idx += stride) {
        out4[idx] = eq4[idx];
    }
}

// ---------------------------------------------------------------------------
// Kernel 3: edge message pass + scatter-add
//   block = 128 threads; thread t owns feature column t of all 3 segments.
//   w_rbf columns held in registers (60 regs), reused across every edge.
// ---------------------------------------------------------------------------
__global__ void __launch_bounds__(128, 4)
edge_kernel(const float* __restrict__ pos,
            const float* __restrict__ eq,
            const float* __restrict__ w_rbf,
            const float* __restrict__ b_rbf,
            const int* __restrict__ z,
            const int* __restrict__ esrc,
            const int* __restrict__ edst,
            float* __restrict__ out) {
    __shared__ float  s_rbf[BE][NRBF];   // 80B rows -> 16B aligned (float4 ok)
    __shared__ float4 s_reld[BE];        // rel * dist
    __shared__ int    s_src[BE];
    __shared__ int    s_dst[BE];
    __shared__ int    s_zs[BE];

    const int t = threadIdx.x;  // 0..127

    // per-thread w_rbf columns in registers
    float wr0[NRBF], wr1[NRBF], wr2[NRBF];
#pragma unroll
    for (int k = 0; k < NRBF; k++) {
        wr0[k] = w_rbf[k * FD3 + t];
        wr1[k] = w_rbf[k * FD3 + FD + t];
        wr2[k] = w_rbf[k * FD3 + 2 * FD + t];
    }
    const float br0 = b_rbf[t];
    const float br1 = b_rbf[FD + t];
    const float br2 = b_rbf[2 * FD + t];

    float* out_emb = out;
    float* out_eq  = out + (size_t)N_NODES * FD;

    const int nb = (N_EDGES + BE - 1) / BE;
    for (int batch = blockIdx.x; batch < nb; batch += gridDim.x) {
        __syncthreads();  // protect smem from previous iteration's readers
        if (t < BE) {
            int e = batch * BE + t;
            if (e < N_EDGES) {
                int s = esrc[e];
                int d = edst[e];
                float psx = pos[s * 3 + 0], psy = pos[s * 3 + 1], psz = pos[s * 3 + 2];
                float pdx = pos[d * 3 + 0], pdy = pos[d * 3 + 1], pdz = pos[d * 3 + 2];
                float rx = pdx - psx, ry = pdy - psy, rz = pdz - psz;
                float dist = sqrtf(rx * rx + ry * ry + rz * rz);
                float invd = 1.0f / dist;
#pragma unroll
                for (int n = 0; n < NRBF; n++)
                    s_rbf[t][n] = sinf((float)(n + 1) * (PI_F / CUTOFF) * dist) * invd;
                s_reld[t] = make_float4(rx * dist, ry * dist, rz * dist, dist);
                s_src[t] = s;
                s_dst[t] = d;
                s_zs[t]  = z[s];
            }
        }
        __syncthreads();

        const int elim = min(BE, N_EDGES - batch * BE);
#pragma unroll 2
        for (int e = 0; e < elim; e++) {
            const int zs  = s_zs[e];
            const int src = s_src[e];
            const int dst = s_dst[e];
            const float* prow = g_phi_table + zs * FD3;
            float p0 = prow[t];
            float p1 = prow[FD + t];
            float p2 = prow[2 * FD + t];

            float W0 = br0, W1 = br1, W2 = br2;
            const float4* r4 = (const float4*)s_rbf[e];
#pragma unroll
            for (int kk = 0; kk < NRBF / 4; kk++) {
                float4 r = r4[kk];
                W0 += r.x * wr0[4 * kk + 0]; W1 += r.x * wr1[4 * kk + 0]; W2 += r.x * wr2[4 * kk + 0];
                W0 += r.y * wr0[4 * kk + 1]; W1 += r.y * wr1[4 * kk + 1]; W2 += r.y * wr2[4 * kk + 1];
                W0 += r.z * wr0[4 * kk + 2]; W1 += r.z * wr1[4 * kk + 2]; W2 += r.z * wr2[4 * kk + 2];
                W0 += r.w * wr0[4 * kk + 3]; W1 += r.w * wr1[4 * kk + 3]; W2 += r.w * wr2[4 * kk + 3];
            }
            float s0 = p0 * W0;   // split[:, :F]
            float s1 = p1 * W1;   // split[:, F:2F]
            float s2 = p2 * W2;   // split[:, 2F:]

            atomicAdd(out_emb + (size_t)dst * FD + t, s0);

            const float* eqr = eq + ((size_t)src * FD + t) * 3;
            float4 rd = s_reld[e];
            float v0 = eqr[0] * s1 + s2 * rd.x;
            float v1 = eqr[1] * s1 + s2 * rd.y;
            float v2 = eqr[2] * s1 + s2 * rd.z;
            float* oq = out_eq + ((size_t)dst * FD + t) * 3;
            atomicAdd(oq + 0, v0);
            atomicAdd(oq + 1, v1);
            atomicAdd(oq + 2, v2);
        }
    }
}

// ---------------------------------------------------------------------------
extern "C" void kernel_launch(void* const* d_in, const int* in_sizes, int n_in,
                              void* d_out, int out_size) {
    const float* pos       = (const float*)d_in[0];
    const float* eq        = (const float*)d_in[1];
    const float* emb_table = (const float*)d_in[2];
    const float* w_phi1    = (const float*)d_in[3];
    const float* b_phi1    = (const float*)d_in[4];
    const float* w_phi2    = (const float*)d_in[5];
    const float* b_phi2    = (const float*)d_in[6];
    const float* w_rbf     = (const float*)d_in[7];
    const float* b_rbf     = (const float*)d_in[8];
    const int*   z         = (const int*)d_in[9];
    const int*   edge_src  = (const int*)d_in[10];
    const int*   edge_dst  = (const int*)d_in[11];
    float* out = (float*)d_out;

    phi_table_kernel<<<N_TYPES, FD>>>(emb_table, w_phi1, b_phi1, w_phi2, b_phi2);
    init_out_kernel<<<4736, 256>>>(out, emb_table, eq, z);
    edge_kernel<<<1776, 128>>>(pos, eq, w_rbf, b_rbf, z, edge_src, edge_dst, out);
}